// round 1
// baseline (speedup 1.0000x reference)
#include <cuda_runtime.h>
#include <math.h>
#include <stdint.h>

// Problem constants
#define BB   2
#define LL   1024
#define DD   768
#define HH   12
#define HD   64
#define NLAY 2
#define DFFN 3072
#define VV   50257
#define EOS_ID 50256
#define ROWS (BB*LL)          // 2048

// ---------------------------------------------------------------------------
// Static scratch (allocation-free per harness rules)
// ---------------------------------------------------------------------------
__device__ float g_x[ROWS*DD];          //  6.3 MB residual stream
__device__ float g_qkv[ROWS*3*DD];      // 18.9 MB qkv
__device__ float g_att[ROWS*DD];        //  6.3 MB attention out (pre-proj)
__device__ float g_tmp[ROWS*DD];        //  6.3 MB proj outputs
__device__ float g_ff[ROWS*DFFN];       // 25.2 MB ff1 out
__device__ int   g_rel[ROWS];
__device__ int   g_seg[ROWS];

// ---------------------------------------------------------------------------
// Meta: rel position within document + segment id (inclusive cummax/cumsum)
// ---------------------------------------------------------------------------
__global__ void meta_kernel(const int* __restrict__ ids, int* __restrict__ rel,
                            int* __restrict__ seg) {
    int b = blockIdx.x;
    if (threadIdx.x != 0) return;
    int last = 0, s = 0;
    for (int l = 0; l < LL; l++) {
        int id = ids[b*LL + l];
        if (id == EOS_ID) { last = l; s += 1; }
        rel[b*LL + l] = l - last;
        seg[b*LL + l] = s;
    }
}

// ---------------------------------------------------------------------------
// Embedding: x = tok_emb[id]*sqrt(D) + pos_emb[rel]
// ---------------------------------------------------------------------------
__global__ void embed_kernel(const int* __restrict__ ids, const int* __restrict__ rel,
                             const float* __restrict__ tok, const float* __restrict__ pos,
                             float* __restrict__ x) {
    int row = blockIdx.x;
    int id = ids[row];
    int r  = rel[row];
    const float* t = tok + (size_t)id * DD;
    const float* p = pos + (size_t)r  * DD;
    const float sc = 27.712812921102035f;  // sqrt(768)
    for (int i = threadIdx.x; i < DD; i += blockDim.x)
        x[(size_t)row*DD + i] = t[i] * sc + p[i];
}

// ---------------------------------------------------------------------------
// SGEMM: C[M,N] = A[M,K] @ B[N,K]^T (+bias) (+exact GELU)
// 128x128 block tile, BK=8, 8x8 per thread, 256 threads.
// M multiple of 128, K multiple of 8 (and 4 for float4). N guarded.
// ---------------------------------------------------------------------------
template<bool GELU>
__global__ __launch_bounds__(256, 2)
void sgemm_bias(const float* __restrict__ A, const float* __restrict__ B,
                const float* __restrict__ bias, float* __restrict__ C,
                int M, int N, int K) {
    const int BM = 128, BN = 128, BK = 8;
    __shared__ float As[BK][BM];
    __shared__ float Bs[BK][BN];

    int bm = blockIdx.y * BM;
    int bn = blockIdx.x * BN;
    int tid = threadIdx.x;
    int tx = tid & 15;        // 0..15 -> N
    int ty = tid >> 4;        // 0..15 -> M

    // Loader mapping: 256 threads, each loads one float4 along K per tile
    int l_row = tid >> 1;           // 0..127
    int l_k4  = (tid & 1) * 4;      // 0 or 4

    float acc[8][8];
#pragma unroll
    for (int i = 0; i < 8; i++)
#pragma unroll
        for (int j = 0; j < 8; j++) acc[i][j] = 0.f;

    const float* Aptr = A + (size_t)(bm + l_row) * K + l_k4;
    int gn = bn + l_row;
    const float* Bptr = (gn < N) ? (B + (size_t)gn * K + l_k4) : nullptr;

    for (int kt = 0; kt < K; kt += BK) {
        float4 av = *reinterpret_cast<const float4*>(Aptr + kt);
        As[l_k4+0][l_row] = av.x; As[l_k4+1][l_row] = av.y;
        As[l_k4+2][l_row] = av.z; As[l_k4+3][l_row] = av.w;

        float4 bv = make_float4(0.f, 0.f, 0.f, 0.f);
        if (Bptr) bv = *reinterpret_cast<const float4*>(Bptr + kt);
        Bs[l_k4+0][l_row] = bv.x; Bs[l_k4+1][l_row] = bv.y;
        Bs[l_k4+2][l_row] = bv.z; Bs[l_k4+3][l_row] = bv.w;
        __syncthreads();

#pragma unroll
        for (int k = 0; k < BK; k++) {
            float ar[8], br[8];
#pragma unroll
            for (int i = 0; i < 8; i++) ar[i] = As[k][ty*8 + i];
#pragma unroll
            for (int j = 0; j < 8; j++) br[j] = Bs[k][tx*8 + j];
#pragma unroll
            for (int i = 0; i < 8; i++)
#pragma unroll
                for (int j = 0; j < 8; j++)
                    acc[i][j] = fmaf(ar[i], br[j], acc[i][j]);
        }
        __syncthreads();
    }

#pragma unroll
    for (int i = 0; i < 8; i++) {
        int row = bm + ty*8 + i;
#pragma unroll
        for (int j = 0; j < 8; j++) {
            int col = bn + tx*8 + j;
            if (col < N) {
                float v = acc[i][j];
                if (bias) v += bias[col];
                if (GELU) v = 0.5f * v * (1.0f + erff(v * 0.7071067811865475f));
                C[(size_t)row * N + col] = v;
            }
        }
    }
}

// ---------------------------------------------------------------------------
// Block reductions (256 threads)
// ---------------------------------------------------------------------------
__device__ __forceinline__ float block_max256(float v, volatile float* red) {
#pragma unroll
    for (int o = 16; o; o >>= 1) v = fmaxf(v, __shfl_xor_sync(0xffffffffu, v, o));
    if ((threadIdx.x & 31) == 0) red[threadIdx.x >> 5] = v;
    __syncthreads();
    if (threadIdx.x == 0) {
        float m = red[0];
#pragma unroll
        for (int i = 1; i < 8; i++) m = fmaxf(m, red[i]);
        red[0] = m;
    }
    __syncthreads();
    float r = red[0];
    __syncthreads();
    return r;
}

__device__ __forceinline__ float block_sum256(float v, volatile float* red) {
#pragma unroll
    for (int o = 16; o; o >>= 1) v += __shfl_xor_sync(0xffffffffu, v, o);
    if ((threadIdx.x & 31) == 0) red[threadIdx.x >> 5] = v;
    __syncthreads();
    if (threadIdx.x == 0) {
        float s = red[0];
#pragma unroll
        for (int i = 1; i < 8; i++) s += red[i];
        red[0] = s;
    }
    __syncthreads();
    float r = red[0];
    __syncthreads();
    return r;
}

// ---------------------------------------------------------------------------
// Fused attention: one block per (b, h, qpos). scores -> softmax -> AV.
// Segment-causal mask: allowed iff k <= q && seg[k]==seg[q].
// ---------------------------------------------------------------------------
__global__ __launch_bounds__(256)
void attn_kernel(const float* __restrict__ qkv, const int* __restrict__ seg,
                 float* __restrict__ o) {
    int idx  = blockIdx.x;
    int qpos = idx % LL;  idx /= LL;
    int h    = idx % HH;
    int b    = idx / HH;
    int tid  = threadIdx.x;

    __shared__ float qs[HD];
    __shared__ float sc[LL];
    __shared__ float red[8];
    __shared__ float part[4][HD];

    const size_t rowQ = (size_t)(b*LL + qpos) * (3*DD);
    if (tid < HD) qs[tid] = qkv[rowQ + h*HD + tid];
    __syncthreads();

    int myseg = seg[b*LL + qpos];
    const float scale = 0.125f;   // 1/sqrt(64)

    // scores (only k <= qpos matter)
    for (int k = tid; k <= qpos; k += 256) {
        float s = -INFINITY;
        if (seg[b*LL + k] == myseg) {
            const float4* kp = reinterpret_cast<const float4*>(
                qkv + (size_t)(b*LL + k) * (3*DD) + DD + h*HD);
            const float4* q4 = reinterpret_cast<const float4*>(qs);
            float d = 0.f;
#pragma unroll
            for (int i = 0; i < HD/4; i++) {
                float4 kv = kp[i], qv = q4[i];
                d = fmaf(kv.x, qv.x, d); d = fmaf(kv.y, qv.y, d);
                d = fmaf(kv.z, qv.z, d); d = fmaf(kv.w, qv.w, d);
            }
            s = d * scale;
        }
        sc[k] = s;
    }
    __syncthreads();

    float m = -INFINITY;
    for (int k = tid; k <= qpos; k += 256) m = fmaxf(m, sc[k]);
    m = block_max256(m, red);

    float su = 0.f;
    for (int k = tid; k <= qpos; k += 256) {
        float e = expf(sc[k] - m);
        sc[k] = e;
        su += e;
    }
    __syncthreads();
    su = block_sum256(su, red);
    float inv = 1.0f / su;

    // AV: 64 dims x 4 k-chunks
    int d = tid & 63;
    int c = tid >> 6;
    float acc = 0.f;
    for (int k = c; k <= qpos; k += 4)
        acc = fmaf(sc[k], qkv[(size_t)(b*LL + k)*(3*DD) + 2*DD + h*HD + d], acc);
    part[c][d] = acc;
    __syncthreads();
    if (tid < HD) {
        float v = (part[0][tid] + part[1][tid] + part[2][tid] + part[3][tid]) * inv;
        o[(size_t)(b*LL + qpos) * DD + h*HD + tid] = v;
    }
}

// ---------------------------------------------------------------------------
// Fused residual add + LayerNorm (post-norm): x = LN(x + r)*w + b
// ---------------------------------------------------------------------------
__global__ __launch_bounds__(256)
void add_ln_kernel(float* __restrict__ x, const float* __restrict__ r,
                   const float* __restrict__ w, const float* __restrict__ b) {
    int row = blockIdx.x;
    int tid = threadIdx.x;
    __shared__ float buf[DD];
    __shared__ float red[8];

    float s = 0.f;
    for (int i = tid; i < DD; i += 256) {
        float v = x[(size_t)row*DD + i] + r[(size_t)row*DD + i];
        buf[i] = v;
        s += v;
    }
    __syncthreads();
    float mean = block_sum256(s, red) * (1.0f / DD);

    float vs = 0.f;
    for (int i = tid; i < DD; i += 256) {
        float d = buf[i] - mean;
        vs += d * d;
    }
    float var = block_sum256(vs, red) * (1.0f / DD);
    float inv = rsqrtf(var + 1e-5f);

    for (int i = tid; i < DD; i += 256)
        x[(size_t)row*DD + i] = (buf[i] - mean) * inv * w[i] + b[i];
}

// ---------------------------------------------------------------------------
// Host launcher
// ---------------------------------------------------------------------------
extern "C" void kernel_launch(void* const* d_in, const int* in_sizes, int n_in,
                              void* d_out, int out_size) {
    const int*   ids   = (const int*)  d_in[0];
    const float* tok   = (const float*)d_in[1];
    const float* pos   = (const float*)d_in[2];
    const float* qkv_w = (const float*)d_in[3];
    const float* qkv_b = (const float*)d_in[4];
    const float* out_w = (const float*)d_in[5];
    const float* out_b = (const float*)d_in[6];
    const float* ln1_w = (const float*)d_in[7];
    const float* ln1_b = (const float*)d_in[8];
    const float* ln2_w = (const float*)d_in[9];
    const float* ln2_b = (const float*)d_in[10];
    const float* ff1_w = (const float*)d_in[11];
    const float* ff1_b = (const float*)d_in[12];
    const float* ff2_w = (const float*)d_in[13];
    const float* ff2_b = (const float*)d_in[14];
    float* out = (float*)d_out;

    float *x, *qkv, *att, *tmp, *ff;
    int *rel, *seg;
    cudaGetSymbolAddress((void**)&x,   g_x);
    cudaGetSymbolAddress((void**)&qkv, g_qkv);
    cudaGetSymbolAddress((void**)&att, g_att);
    cudaGetSymbolAddress((void**)&tmp, g_tmp);
    cudaGetSymbolAddress((void**)&ff,  g_ff);
    cudaGetSymbolAddress((void**)&rel, g_rel);
    cudaGetSymbolAddress((void**)&seg, g_seg);

    meta_kernel<<<BB, 32>>>(ids, rel, seg);
    embed_kernel<<<ROWS, 256>>>(ids, rel, tok, pos, x);

    for (int l = 0; l < NLAY; l++) {
        // qkv = x @ qkv_w^T + qkv_b   [2048, 2304]
        sgemm_bias<false><<<dim3(3*DD/128, ROWS/128), 256>>>(
            x, qkv_w + (size_t)l*3*DD*DD, qkv_b + (size_t)l*3*DD, qkv,
            ROWS, 3*DD, DD);

        // fused attention
        attn_kernel<<<BB*HH*LL, 256>>>(qkv, seg, att);

        // o = att @ out_w^T + out_b
        sgemm_bias<false><<<dim3(DD/128, ROWS/128), 256>>>(
            att, out_w + (size_t)l*DD*DD, out_b + (size_t)l*DD, tmp,
            ROWS, DD, DD);

        // x = LN(x + o)
        add_ln_kernel<<<ROWS, 256>>>(x, tmp, ln1_w + (size_t)l*DD, ln1_b + (size_t)l*DD);

        // h = gelu(x @ ff1_w^T + ff1_b)   [2048, 3072]
        sgemm_bias<true><<<dim3(DFFN/128, ROWS/128), 256>>>(
            x, ff1_w + (size_t)l*DFFN*DD, ff1_b + (size_t)l*DFFN, ff,
            ROWS, DFFN, DD);

        // h2 = h @ ff2_w^T + ff2_b
        sgemm_bias<false><<<dim3(DD/128, ROWS/128), 256>>>(
            ff, ff2_w + (size_t)l*DD*DFFN, ff2_b + (size_t)l*DD, tmp,
            ROWS, DD, DFFN);

        // x = LN(x + h2)
        add_ln_kernel<<<ROWS, 256>>>(x, tmp, ln2_w + (size_t)l*DD, ln2_b + (size_t)l*DD);
    }

    // logits = x @ tok_emb^T   [2048, 50257]
    sgemm_bias<false><<<dim3((VV + 127)/128, ROWS/128), 256>>>(
        x, tok, nullptr, out, ROWS, VV, DD);
}

// round 2
// speedup vs baseline: 2.5574x; 2.5574x over previous
#include <cuda_runtime.h>
#include <math.h>
#include <stdint.h>

// Problem constants
#define BB   2
#define LL   1024
#define DD   768
#define HH   12
#define HD   64
#define NLAY 2
#define DFFN 3072
#define VV   50257
#define EOS_ID 50256
#define ROWS (BB*LL)          // 2048

// ---------------------------------------------------------------------------
// Static scratch (allocation-free per harness rules)
// ---------------------------------------------------------------------------
__device__ float g_x[ROWS*DD];
__device__ float g_qkv[ROWS*3*DD];
__device__ float g_att[ROWS*DD];
__device__ float g_tmp[ROWS*DD];
__device__ float g_ff[ROWS*DFFN];
__device__ int   g_rel[ROWS];
__device__ int   g_seg[ROWS];

// ---------------------------------------------------------------------------
// Meta: rel position within document + segment id
// ---------------------------------------------------------------------------
__global__ void meta_kernel(const int* __restrict__ ids, int* __restrict__ rel,
                            int* __restrict__ seg) {
    int b = blockIdx.x;
    if (threadIdx.x != 0) return;
    int last = 0, s = 0;
    for (int l = 0; l < LL; l++) {
        int id = ids[b*LL + l];
        if (id == EOS_ID) { last = l; s += 1; }
        rel[b*LL + l] = l - last;
        seg[b*LL + l] = s;
    }
}

// ---------------------------------------------------------------------------
// Embedding
// ---------------------------------------------------------------------------
__global__ void embed_kernel(const int* __restrict__ ids, const int* __restrict__ rel,
                             const float* __restrict__ tok, const float* __restrict__ pos,
                             float* __restrict__ x) {
    int row = blockIdx.x;
    int id = ids[row];
    int r  = rel[row];
    const float* t = tok + (size_t)id * DD;
    const float* p = pos + (size_t)r  * DD;
    const float sc = 27.712812921102035f;  // sqrt(768)
    for (int i = threadIdx.x; i < DD; i += blockDim.x)
        x[(size_t)row*DD + i] = t[i] * sc + p[i];
}

// ---------------------------------------------------------------------------
// TF32 tensor-core GEMM: C[M,N] = A[M,K] @ B[N,K]^T (+bias) (+exact GELU)
// Block tile 128x128, BK=32. 256 threads = 8 warps (4 m x 2 n),
// warp tile 32x64, mma.sync.m16n8k8.tf32, fp32 accumulate.
// M % 128 == 0, K % 32 == 0 required. N guarded.
// ---------------------------------------------------------------------------
#define BKP 36   // padded k-stride (floats): 16B-aligned, conflict-free reads

__device__ __forceinline__ uint32_t f2tf32(float v) {
    uint32_t r;
    asm("cvt.rna.tf32.f32 %0, %1;" : "=r"(r) : "f"(v));
    return r;
}

template<bool GELU>
__global__ __launch_bounds__(256, 1)
void gemm_tf32(const float* __restrict__ A, const float* __restrict__ B,
               const float* __restrict__ bias, float* __restrict__ C,
               int M, int N, int K) {
    __shared__ float As[128*BKP];
    __shared__ float Bs[128*BKP];

    const int bm = blockIdx.y * 128;
    const int bn = blockIdx.x * 128;
    const int tid  = threadIdx.x;
    const int warp = tid >> 5;
    const int lane = tid & 31;
    const int grp  = lane >> 2;     // 0..7
    const int qid  = lane & 3;      // 0..3

    const int wm = (warp >> 1) * 32;   // warp m offset in block tile
    const int wn = (warp & 1) * 64;    // warp n offset

    float acc[2][8][4];
#pragma unroll
    for (int i = 0; i < 2; i++)
#pragma unroll
        for (int j = 0; j < 8; j++)
#pragma unroll
            for (int c = 0; c < 4; c++) acc[i][j][c] = 0.f;

    // Loader mapping: 1024 float4 per tile, 4 per thread
    // idx = tid + i*256 ; row = idx>>3 ; k4 = (idx&7)*4
    const int ntiles = K >> 5;  // K/32

    float4 rA[4], rB[4];

    // ---- load tile 0 ----
#pragma unroll
    for (int i = 0; i < 4; i++) {
        int idx = tid + (i << 8);
        int row = idx >> 3;
        int k4  = (idx & 7) << 2;
        rA[i] = *reinterpret_cast<const float4*>(A + (size_t)(bm + row) * K + k4);
        int gn = bn + row;
        rB[i] = (gn < N) ? *reinterpret_cast<const float4*>(B + (size_t)gn * K + k4)
                         : make_float4(0.f, 0.f, 0.f, 0.f);
    }
#pragma unroll
    for (int i = 0; i < 4; i++) {
        int idx = tid + (i << 8);
        int row = idx >> 3;
        int k4  = (idx & 7) << 2;
        *reinterpret_cast<float4*>(&As[row*BKP + k4]) = rA[i];
        *reinterpret_cast<float4*>(&Bs[row*BKP + k4]) = rB[i];
    }
    __syncthreads();

    for (int t = 0; t < ntiles; t++) {
        // prefetch next tile into registers
        if (t + 1 < ntiles) {
            int kt = (t + 1) << 5;
#pragma unroll
            for (int i = 0; i < 4; i++) {
                int idx = tid + (i << 8);
                int row = idx >> 3;
                int k4  = (idx & 7) << 2;
                rA[i] = *reinterpret_cast<const float4*>(A + (size_t)(bm + row) * K + kt + k4);
                int gn = bn + row;
                rB[i] = (gn < N) ? *reinterpret_cast<const float4*>(B + (size_t)gn * K + kt + k4)
                                 : make_float4(0.f, 0.f, 0.f, 0.f);
            }
        }

        // compute: 4 k-steps of 8
#pragma unroll
        for (int ks = 0; ks < 4; ks++) {
            int k0 = ks << 3;
            uint32_t af[2][4];
#pragma unroll
            for (int i = 0; i < 2; i++) {
                int r0 = wm + i*16 + grp;
                af[i][0] = f2tf32(As[(r0    )*BKP + k0 + qid    ]);
                af[i][1] = f2tf32(As[(r0 + 8)*BKP + k0 + qid    ]);
                af[i][2] = f2tf32(As[(r0    )*BKP + k0 + qid + 4]);
                af[i][3] = f2tf32(As[(r0 + 8)*BKP + k0 + qid + 4]);
            }
#pragma unroll
            for (int j = 0; j < 8; j++) {
                int nrow = wn + j*8 + grp;
                uint32_t b0 = f2tf32(Bs[nrow*BKP + k0 + qid    ]);
                uint32_t b1 = f2tf32(Bs[nrow*BKP + k0 + qid + 4]);
#pragma unroll
                for (int i = 0; i < 2; i++) {
                    asm volatile(
                        "mma.sync.aligned.m16n8k8.row.col.f32.tf32.tf32.f32 "
                        "{%0,%1,%2,%3}, {%4,%5,%6,%7}, {%8,%9}, {%0,%1,%2,%3};\n"
                        : "+f"(acc[i][j][0]), "+f"(acc[i][j][1]),
                          "+f"(acc[i][j][2]), "+f"(acc[i][j][3])
                        : "r"(af[i][0]), "r"(af[i][1]), "r"(af[i][2]), "r"(af[i][3]),
                          "r"(b0), "r"(b1));
                }
            }
        }
        __syncthreads();

        if (t + 1 < ntiles) {
#pragma unroll
            for (int i = 0; i < 4; i++) {
                int idx = tid + (i << 8);
                int row = idx >> 3;
                int k4  = (idx & 7) << 2;
                *reinterpret_cast<float4*>(&As[row*BKP + k4]) = rA[i];
                *reinterpret_cast<float4*>(&Bs[row*BKP + k4]) = rB[i];
            }
            __syncthreads();
        }
    }

    // epilogue
#pragma unroll
    for (int i = 0; i < 2; i++) {
#pragma unroll
        for (int j = 0; j < 8; j++) {
#pragma unroll
            for (int c = 0; c < 4; c++) {
                int row = bm + wm + i*16 + grp + ((c >> 1) << 3);      // +8 for c2,c3
                int col = bn + wn + j*8 + (qid << 1) + (c & 1);
                if (col < N) {
                    float v = acc[i][j][c];
                    if (bias) v += bias[col];
                    if (GELU) v = 0.5f * v * (1.0f + erff(v * 0.7071067811865475f));
                    C[(size_t)row * N + col] = v;
                }
            }
        }
    }
}

// ---------------------------------------------------------------------------
// Block reductions (256 threads)
// ---------------------------------------------------------------------------
__device__ __forceinline__ float block_max256(float v, volatile float* red) {
#pragma unroll
    for (int o = 16; o; o >>= 1) v = fmaxf(v, __shfl_xor_sync(0xffffffffu, v, o));
    if ((threadIdx.x & 31) == 0) red[threadIdx.x >> 5] = v;
    __syncthreads();
    if (threadIdx.x == 0) {
        float m = red[0];
#pragma unroll
        for (int i = 1; i < 8; i++) m = fmaxf(m, red[i]);
        red[0] = m;
    }
    __syncthreads();
    float r = red[0];
    __syncthreads();
    return r;
}

__device__ __forceinline__ float block_sum256(float v, volatile float* red) {
#pragma unroll
    for (int o = 16; o; o >>= 1) v += __shfl_xor_sync(0xffffffffu, v, o);
    if ((threadIdx.x & 31) == 0) red[threadIdx.x >> 5] = v;
    __syncthreads();
    if (threadIdx.x == 0) {
        float s = red[0];
#pragma unroll
        for (int i = 1; i < 8; i++) s += red[i];
        red[0] = s;
    }
    __syncthreads();
    float r = red[0];
    __syncthreads();
    return r;
}

// ---------------------------------------------------------------------------
// Fused attention: one block per (b, h, qpos)
// ---------------------------------------------------------------------------
__global__ __launch_bounds__(256)
void attn_kernel(const float* __restrict__ qkv, const int* __restrict__ seg,
                 float* __restrict__ o) {
    int idx  = blockIdx.x;
    int qpos = idx % LL;  idx /= LL;
    int h    = idx % HH;
    int b    = idx / HH;
    int tid  = threadIdx.x;

    __shared__ float qs[HD];
    __shared__ float sc[LL];
    __shared__ float red[8];
    __shared__ float part[4][HD];

    const size_t rowQ = (size_t)(b*LL + qpos) * (3*DD);
    if (tid < HD) qs[tid] = qkv[rowQ + h*HD + tid];
    __syncthreads();

    int myseg = seg[b*LL + qpos];
    const float scale = 0.125f;

    for (int k = tid; k <= qpos; k += 256) {
        float s = -INFINITY;
        if (seg[b*LL + k] == myseg) {
            const float4* kp = reinterpret_cast<const float4*>(
                qkv + (size_t)(b*LL + k) * (3*DD) + DD + h*HD);
            const float4* q4 = reinterpret_cast<const float4*>(qs);
            float d = 0.f;
#pragma unroll
            for (int i = 0; i < HD/4; i++) {
                float4 kv = kp[i], qv = q4[i];
                d = fmaf(kv.x, qv.x, d); d = fmaf(kv.y, qv.y, d);
                d = fmaf(kv.z, qv.z, d); d = fmaf(kv.w, qv.w, d);
            }
            s = d * scale;
        }
        sc[k] = s;
    }
    __syncthreads();

    float m = -INFINITY;
    for (int k = tid; k <= qpos; k += 256) m = fmaxf(m, sc[k]);
    m = block_max256(m, red);

    float su = 0.f;
    for (int k = tid; k <= qpos; k += 256) {
        float e = expf(sc[k] - m);
        sc[k] = e;
        su += e;
    }
    __syncthreads();
    su = block_sum256(su, red);
    float inv = 1.0f / su;

    int d = tid & 63;
    int c = tid >> 6;
    float acc = 0.f;
    for (int k = c; k <= qpos; k += 4)
        acc = fmaf(sc[k], qkv[(size_t)(b*LL + k)*(3*DD) + 2*DD + h*HD + d], acc);
    part[c][d] = acc;
    __syncthreads();
    if (tid < HD) {
        float v = (part[0][tid] + part[1][tid] + part[2][tid] + part[3][tid]) * inv;
        o[(size_t)(b*LL + qpos) * DD + h*HD + tid] = v;
    }
}

// ---------------------------------------------------------------------------
// Fused residual add + LayerNorm
// ---------------------------------------------------------------------------
__global__ __launch_bounds__(256)
void add_ln_kernel(float* __restrict__ x, const float* __restrict__ r,
                   const float* __restrict__ w, const float* __restrict__ b) {
    int row = blockIdx.x;
    int tid = threadIdx.x;
    __shared__ float buf[DD];
    __shared__ float red[8];

    float s = 0.f;
    for (int i = tid; i < DD; i += 256) {
        float v = x[(size_t)row*DD + i] + r[(size_t)row*DD + i];
        buf[i] = v;
        s += v;
    }
    __syncthreads();
    float mean = block_sum256(s, red) * (1.0f / DD);

    float vs = 0.f;
    for (int i = tid; i < DD; i += 256) {
        float d = buf[i] - mean;
        vs += d * d;
    }
    float var = block_sum256(vs, red) * (1.0f / DD);
    float inv = rsqrtf(var + 1e-5f);

    for (int i = tid; i < DD; i += 256)
        x[(size_t)row*DD + i] = (buf[i] - mean) * inv * w[i] + b[i];
}

// ---------------------------------------------------------------------------
// Host launcher
// ---------------------------------------------------------------------------
extern "C" void kernel_launch(void* const* d_in, const int* in_sizes, int n_in,
                              void* d_out, int out_size) {
    const int*   ids   = (const int*)  d_in[0];
    const float* tok   = (const float*)d_in[1];
    const float* pos   = (const float*)d_in[2];
    const float* qkv_w = (const float*)d_in[3];
    const float* qkv_b = (const float*)d_in[4];
    const float* out_w = (const float*)d_in[5];
    const float* out_b = (const float*)d_in[6];
    const float* ln1_w = (const float*)d_in[7];
    const float* ln1_b = (const float*)d_in[8];
    const float* ln2_w = (const float*)d_in[9];
    const float* ln2_b = (const float*)d_in[10];
    const float* ff1_w = (const float*)d_in[11];
    const float* ff1_b = (const float*)d_in[12];
    const float* ff2_w = (const float*)d_in[13];
    const float* ff2_b = (const float*)d_in[14];
    float* out = (float*)d_out;

    float *x, *qkv, *att, *tmp, *ff;
    int *rel, *seg;
    cudaGetSymbolAddress((void**)&x,   g_x);
    cudaGetSymbolAddress((void**)&qkv, g_qkv);
    cudaGetSymbolAddress((void**)&att, g_att);
    cudaGetSymbolAddress((void**)&tmp, g_tmp);
    cudaGetSymbolAddress((void**)&ff,  g_ff);
    cudaGetSymbolAddress((void**)&rel, g_rel);
    cudaGetSymbolAddress((void**)&seg, g_seg);

    meta_kernel<<<BB, 32>>>(ids, rel, seg);
    embed_kernel<<<ROWS, 256>>>(ids, rel, tok, pos, x);

    for (int l = 0; l < NLAY; l++) {
        gemm_tf32<false><<<dim3(3*DD/128, ROWS/128), 256>>>(
            x, qkv_w + (size_t)l*3*DD*DD, qkv_b + (size_t)l*3*DD, qkv,
            ROWS, 3*DD, DD);

        attn_kernel<<<BB*HH*LL, 256>>>(qkv, seg, att);

        gemm_tf32<false><<<dim3(DD/128, ROWS/128), 256>>>(
            att, out_w + (size_t)l*DD*DD, out_b + (size_t)l*DD, tmp,
            ROWS, DD, DD);

        add_ln_kernel<<<ROWS, 256>>>(x, tmp, ln1_w + (size_t)l*DD, ln1_b + (size_t)l*DD);

        gemm_tf32<true><<<dim3(DFFN/128, ROWS/128), 256>>>(
            x, ff1_w + (size_t)l*DFFN*DD, ff1_b + (size_t)l*DFFN, ff,
            ROWS, DFFN, DD);

        gemm_tf32<false><<<dim3(DD/128, ROWS/128), 256>>>(
            ff, ff2_w + (size_t)l*DD*DFFN, ff2_b + (size_t)l*DD, tmp,
            ROWS, DD, DFFN);

        add_ln_kernel<<<ROWS, 256>>>(x, tmp, ln2_w + (size_t)l*DD, ln2_b + (size_t)l*DD);
    }

    gemm_tf32<false><<<dim3((VV + 127)/128, ROWS/128), 256>>>(
        x, tok, nullptr, out, ROWS, VV, DD);
}

// round 3
// speedup vs baseline: 3.4478x; 1.3482x over previous
#include <cuda_runtime.h>
#include <math.h>
#include <stdint.h>

// Problem constants
#define BB   2
#define LL   1024
#define DD   768
#define HH   12
#define HD   64
#define NLAY 2
#define DFFN 3072
#define VV   50257
#define EOS_ID 50256
#define ROWS (BB*LL)          // 2048

// ---------------------------------------------------------------------------
// Static scratch
// ---------------------------------------------------------------------------
__device__ float g_x[ROWS*DD];
__device__ float g_qkv[ROWS*3*DD];
__device__ float g_att[ROWS*DD];
__device__ float g_tmp[ROWS*DD];
__device__ float g_ff[ROWS*DFFN];
__device__ int   g_rel[ROWS];
__device__ int   g_seg[ROWS];

// ---------------------------------------------------------------------------
// Meta
// ---------------------------------------------------------------------------
__global__ void meta_kernel(const int* __restrict__ ids, int* __restrict__ rel,
                            int* __restrict__ seg) {
    int b = blockIdx.x;
    if (threadIdx.x != 0) return;
    int last = 0, s = 0;
    for (int l = 0; l < LL; l++) {
        int id = ids[b*LL + l];
        if (id == EOS_ID) { last = l; s += 1; }
        rel[b*LL + l] = l - last;
        seg[b*LL + l] = s;
    }
}

// ---------------------------------------------------------------------------
// Embedding
// ---------------------------------------------------------------------------
__global__ void embed_kernel(const int* __restrict__ ids, const int* __restrict__ rel,
                             const float* __restrict__ tok, const float* __restrict__ pos,
                             float* __restrict__ x) {
    int row = blockIdx.x;
    int id = ids[row];
    int r  = rel[row];
    const float* t = tok + (size_t)id * DD;
    const float* p = pos + (size_t)r  * DD;
    const float sc = 27.712812921102035f;  // sqrt(768)
    for (int i = threadIdx.x; i < DD; i += blockDim.x)
        x[(size_t)row*DD + i] = t[i] * sc + p[i];
}

// ---------------------------------------------------------------------------
// TF32 tensor-core GEMM: C[M,N] = A[M,K] @ B[N,K]^T (+bias) (+exact GELU)
// Block tile 128x128, BK=32, 8 warps, warp tile 32x64, m16n8k8 mma.
// Pre-converted tf32 in smem, double-buffered. M%128==0, K%32==0, N guarded.
// ---------------------------------------------------------------------------
#define BKP 36
#define GEMM_SMEM (4*128*BKP*4)   // 2 buffers x (A+B) x 128*BKP floats

__device__ __forceinline__ uint32_t f2tf32(float v) {
    uint32_t r;
    asm("cvt.rna.tf32.f32 %0, %1;" : "=r"(r) : "f"(v));
    return r;
}

template<bool GELU>
__global__ __launch_bounds__(256, 2)
void gemm_tf32(const float* __restrict__ A, const float* __restrict__ B,
               const float* __restrict__ bias, float* __restrict__ C,
               int M, int N, int K) {
    extern __shared__ uint32_t gsm[];
    const int TILE = 128*BKP;

    const int bm = blockIdx.y * 128;
    const int bn = blockIdx.x * 128;
    const int tid  = threadIdx.x;
    const int warp = tid >> 5;
    const int lane = tid & 31;
    const int grp  = lane >> 2;
    const int qid  = lane & 3;

    const int wm = (warp >> 1) * 32;
    const int wn = (warp & 1) * 64;

    float acc[2][8][4];
#pragma unroll
    for (int i = 0; i < 2; i++)
#pragma unroll
        for (int j = 0; j < 8; j++)
#pragma unroll
            for (int c = 0; c < 4; c++) acc[i][j][c] = 0.f;

    const int ntiles = K >> 5;
    const int l_row = tid >> 1;          // 0..127
    const int l_k4  = (tid & 1) << 2;    // 0 or 4 (x2 float4 slots of 8 along 32)

    float4 rA[4], rB[4];

    // ---- prologue: gmem tile 0 -> regs -> smem[0]
#pragma unroll
    for (int i = 0; i < 4; i++) {
        int idx = tid + (i << 8);
        int row = idx >> 3;
        int k4  = (idx & 7) << 2;
        rA[i] = *reinterpret_cast<const float4*>(A + (size_t)(bm + row) * K + k4);
        int gn = bn + row;
        rB[i] = (gn < N) ? *reinterpret_cast<const float4*>(B + (size_t)gn * K + k4)
                         : make_float4(0.f, 0.f, 0.f, 0.f);
    }
#pragma unroll
    for (int i = 0; i < 4; i++) {
        int idx = tid + (i << 8);
        int row = idx >> 3;
        int k4  = (idx & 7) << 2;
        uint32_t* a = gsm + row*BKP + k4;
        a[0] = f2tf32(rA[i].x); a[1] = f2tf32(rA[i].y);
        a[2] = f2tf32(rA[i].z); a[3] = f2tf32(rA[i].w);
        uint32_t* bb = gsm + TILE + row*BKP + k4;
        bb[0] = f2tf32(rB[i].x); bb[1] = f2tf32(rB[i].y);
        bb[2] = f2tf32(rB[i].z); bb[3] = f2tf32(rB[i].w);
    }

    for (int t = 0; t < ntiles; t++) {
        __syncthreads();
        const uint32_t* As = gsm + (t & 1) * 2 * TILE;
        const uint32_t* Bs = As + TILE;

        // prefetch next tile gmem -> regs
        if (t + 1 < ntiles) {
            int kt = (t + 1) << 5;
#pragma unroll
            for (int i = 0; i < 4; i++) {
                int idx = tid + (i << 8);
                int row = idx >> 3;
                int k4  = (idx & 7) << 2;
                rA[i] = *reinterpret_cast<const float4*>(A + (size_t)(bm + row) * K + kt + k4);
                int gn = bn + row;
                rB[i] = (gn < N) ? *reinterpret_cast<const float4*>(B + (size_t)gn * K + kt + k4)
                                 : make_float4(0.f, 0.f, 0.f, 0.f);
            }
        }

        // compute 4 k8-steps
#pragma unroll
        for (int ks = 0; ks < 4; ks++) {
            int k0 = ks << 3;
            uint32_t af[2][4];
#pragma unroll
            for (int i = 0; i < 2; i++) {
                int r0 = wm + i*16 + grp;
                af[i][0] = As[(r0    )*BKP + k0 + qid    ];
                af[i][1] = As[(r0 + 8)*BKP + k0 + qid    ];
                af[i][2] = As[(r0    )*BKP + k0 + qid + 4];
                af[i][3] = As[(r0 + 8)*BKP + k0 + qid + 4];
            }
#pragma unroll
            for (int j = 0; j < 8; j++) {
                int nrow = wn + j*8 + grp;
                uint32_t b0 = Bs[nrow*BKP + k0 + qid    ];
                uint32_t b1 = Bs[nrow*BKP + k0 + qid + 4];
#pragma unroll
                for (int i = 0; i < 2; i++) {
                    asm volatile(
                        "mma.sync.aligned.m16n8k8.row.col.f32.tf32.tf32.f32 "
                        "{%0,%1,%2,%3}, {%4,%5,%6,%7}, {%8,%9}, {%0,%1,%2,%3};\n"
                        : "+f"(acc[i][j][0]), "+f"(acc[i][j][1]),
                          "+f"(acc[i][j][2]), "+f"(acc[i][j][3])
                        : "r"(af[i][0]), "r"(af[i][1]), "r"(af[i][2]), "r"(af[i][3]),
                          "r"(b0), "r"(b1));
                }
            }
        }

        // store prefetched tile to the other buffer
        if (t + 1 < ntiles) {
            uint32_t* An = gsm + ((t + 1) & 1) * 2 * TILE;
            uint32_t* Bn = An + TILE;
#pragma unroll
            for (int i = 0; i < 4; i++) {
                int idx = tid + (i << 8);
                int row = idx >> 3;
                int k4  = (idx & 7) << 2;
                uint32_t* a = An + row*BKP + k4;
                a[0] = f2tf32(rA[i].x); a[1] = f2tf32(rA[i].y);
                a[2] = f2tf32(rA[i].z); a[3] = f2tf32(rA[i].w);
                uint32_t* bb = Bn + row*BKP + k4;
                bb[0] = f2tf32(rB[i].x); bb[1] = f2tf32(rB[i].y);
                bb[2] = f2tf32(rB[i].z); bb[3] = f2tf32(rB[i].w);
            }
        }
    }

    // epilogue
#pragma unroll
    for (int i = 0; i < 2; i++) {
#pragma unroll
        for (int j = 0; j < 8; j++) {
#pragma unroll
            for (int c = 0; c < 4; c++) {
                int row = bm + wm + i*16 + grp + ((c >> 1) << 3);
                int col = bn + wn + j*8 + (qid << 1) + (c & 1);
                if (col < N) {
                    float v = acc[i][j][c];
                    if (bias) v += bias[col];
                    if (GELU) v = 0.5f * v * (1.0f + erff(v * 0.7071067811865475f));
                    C[(size_t)row * N + col] = v;
                }
            }
        }
    }
}

// ---------------------------------------------------------------------------
// Tiled flash attention: block = (qtile 64, h, b). 256 threads, 4x4/thread.
// K/V tiles in smem (reused by 64 queries), online softmax in registers.
// ---------------------------------------------------------------------------
#define APAD 68
#define ATTN_SMEM (4*64*APAD*4 + 64*4)

__global__ __launch_bounds__(256, 2)
void attn_tile_kernel(const float* __restrict__ qkv, const int* __restrict__ seg,
                      float* __restrict__ o) {
    extern __shared__ float asm_[];
    float* Qt = asm_;                 // [d][q] transposed
    float* Kt = Qt + 64*APAD;         // [d][k] transposed
    float* Vs = Kt + 64*APAD;         // [k][d]
    float* Ps = Vs + 64*APAD;         // [q][k]
    int*  sseg = (int*)(Ps + 64*APAD);

    const int qt = blockIdx.x;
    const int h  = blockIdx.y;
    const int b  = blockIdx.z;
    const int tid = threadIdx.x;
    const int tx = tid & 15, ty = tid >> 4;
    const int q0 = qt * 64;

    // load Q transposed
#pragma unroll
    for (int i = 0; i < 4; i++) {
        int idx = tid + (i << 8);
        int r = idx >> 4;
        int c = (idx & 15) << 2;
        float4 v = *reinterpret_cast<const float4*>(
            qkv + (size_t)(b*LL + q0 + r)*(3*DD) + h*HD + c);
        Qt[(c+0)*APAD + r] = v.x;
        Qt[(c+1)*APAD + r] = v.y;
        Qt[(c+2)*APAD + r] = v.z;
        Qt[(c+3)*APAD + r] = v.w;
    }
    int qseg[4];
#pragma unroll
    for (int i = 0; i < 4; i++) qseg[i] = seg[b*LL + q0 + 4*ty + i];

    float m[4], l[4], O[4][4];
#pragma unroll
    for (int i = 0; i < 4; i++) {
        m[i] = -1e30f; l[i] = 0.f;
#pragma unroll
        for (int j = 0; j < 4; j++) O[i][j] = 0.f;
    }
    __syncthreads();

    for (int kt = 0; kt <= qt; kt++) {
        const int k0 = kt * 64;
        // load K transposed, V natural, seg
#pragma unroll
        for (int i = 0; i < 4; i++) {
            int idx = tid + (i << 8);
            int r = idx >> 4;
            int c = (idx & 15) << 2;
            const float* base = qkv + (size_t)(b*LL + k0 + r)*(3*DD) + h*HD + c;
            float4 kv = *reinterpret_cast<const float4*>(base + DD);
            Kt[(c+0)*APAD + r] = kv.x;
            Kt[(c+1)*APAD + r] = kv.y;
            Kt[(c+2)*APAD + r] = kv.z;
            Kt[(c+3)*APAD + r] = kv.w;
            float4 vv = *reinterpret_cast<const float4*>(base + 2*DD);
            *reinterpret_cast<float4*>(&Vs[r*APAD + c]) = vv;
        }
        if (tid < 64) sseg[tid] = seg[b*LL + k0 + tid];
        __syncthreads();

        // S = Q K^T (4x4 per thread)
        float s[4][4];
#pragma unroll
        for (int i = 0; i < 4; i++)
#pragma unroll
            for (int j = 0; j < 4; j++) s[i][j] = 0.f;
#pragma unroll 8
        for (int d = 0; d < 64; d++) {
            float4 qv = *reinterpret_cast<const float4*>(&Qt[d*APAD + 4*ty]);
            float4 kv = *reinterpret_cast<const float4*>(&Kt[d*APAD + 4*tx]);
            float qa[4] = {qv.x, qv.y, qv.z, qv.w};
            float ka[4] = {kv.x, kv.y, kv.z, kv.w};
#pragma unroll
            for (int i = 0; i < 4; i++)
#pragma unroll
                for (int j = 0; j < 4; j++)
                    s[i][j] = fmaf(qa[i], ka[j], s[i][j]);
        }

        // mask + online softmax (rows = 16 lanes with same ty)
#pragma unroll
        for (int i = 0; i < 4; i++) {
            int qg = q0 + 4*ty + i;
#pragma unroll
            for (int j = 0; j < 4; j++) {
                int kg = k0 + 4*tx + j;
                bool ok = (kg <= qg) && (sseg[4*tx + j] == qseg[i]);
                s[i][j] = ok ? s[i][j] * 0.125f : -1e30f;
            }
            float mt = fmaxf(fmaxf(s[i][0], s[i][1]), fmaxf(s[i][2], s[i][3]));
#pragma unroll
            for (int off = 1; off < 16; off <<= 1)
                mt = fmaxf(mt, __shfl_xor_sync(0xffffffffu, mt, off));
            float mn = fmaxf(m[i], mt);
            float fac = __expf(m[i] - mn);
            m[i] = mn;
            l[i] *= fac;
#pragma unroll
            for (int j = 0; j < 4; j++) O[i][j] *= fac;
            float rs = 0.f;
#pragma unroll
            for (int j = 0; j < 4; j++) {
                float p = __expf(s[i][j] - mn);
                s[i][j] = p;
                rs += p;
            }
#pragma unroll
            for (int off = 1; off < 16; off <<= 1)
                rs += __shfl_xor_sync(0xffffffffu, rs, off);
            l[i] += rs;
        }

        // stage P [q][k]
#pragma unroll
        for (int i = 0; i < 4; i++)
            *reinterpret_cast<float4*>(&Ps[(4*ty + i)*APAD + 4*tx]) =
                make_float4(s[i][0], s[i][1], s[i][2], s[i][3]);
        __syncthreads();

        // O += P @ V
#pragma unroll 4
        for (int k = 0; k < 64; k++) {
            float pa[4];
#pragma unroll
            for (int i = 0; i < 4; i++) pa[i] = Ps[(4*ty + i)*APAD + k];
            float4 vv = *reinterpret_cast<const float4*>(&Vs[k*APAD + 4*tx]);
            float va[4] = {vv.x, vv.y, vv.z, vv.w};
#pragma unroll
            for (int i = 0; i < 4; i++)
#pragma unroll
                for (int j = 0; j < 4; j++)
                    O[i][j] = fmaf(pa[i], va[j], O[i][j]);
        }
        __syncthreads();
    }

    // write out
#pragma unroll
    for (int i = 0; i < 4; i++) {
        float inv = 1.0f / l[i];
        float4 ov = make_float4(O[i][0]*inv, O[i][1]*inv, O[i][2]*inv, O[i][3]*inv);
        *reinterpret_cast<float4*>(
            o + (size_t)(b*LL + q0 + 4*ty + i)*DD + h*HD + 4*tx) = ov;
    }
}

// ---------------------------------------------------------------------------
// Block reduction (256 threads)
// ---------------------------------------------------------------------------
__device__ __forceinline__ float block_sum256(float v, volatile float* red) {
#pragma unroll
    for (int o = 16; o; o >>= 1) v += __shfl_xor_sync(0xffffffffu, v, o);
    if ((threadIdx.x & 31) == 0) red[threadIdx.x >> 5] = v;
    __syncthreads();
    if (threadIdx.x == 0) {
        float s = red[0];
#pragma unroll
        for (int i = 1; i < 8; i++) s += red[i];
        red[0] = s;
    }
    __syncthreads();
    float r = red[0];
    __syncthreads();
    return r;
}

// ---------------------------------------------------------------------------
// Fused residual add + LayerNorm
// ---------------------------------------------------------------------------
__global__ __launch_bounds__(256)
void add_ln_kernel(float* __restrict__ x, const float* __restrict__ r,
                   const float* __restrict__ w, const float* __restrict__ b) {
    int row = blockIdx.x;
    int tid = threadIdx.x;
    __shared__ float buf[DD];
    __shared__ float red[8];

    float s = 0.f;
    for (int i = tid; i < DD; i += 256) {
        float v = x[(size_t)row*DD + i] + r[(size_t)row*DD + i];
        buf[i] = v;
        s += v;
    }
    __syncthreads();
    float mean = block_sum256(s, red) * (1.0f / DD);

    float vs = 0.f;
    for (int i = tid; i < DD; i += 256) {
        float d = buf[i] - mean;
        vs += d * d;
    }
    float var = block_sum256(vs, red) * (1.0f / DD);
    float inv = rsqrtf(var + 1e-5f);

    for (int i = tid; i < DD; i += 256)
        x[(size_t)row*DD + i] = (buf[i] - mean) * inv * w[i] + b[i];
}

// ---------------------------------------------------------------------------
// Host launcher
// ---------------------------------------------------------------------------
extern "C" void kernel_launch(void* const* d_in, const int* in_sizes, int n_in,
                              void* d_out, int out_size) {
    const int*   ids   = (const int*)  d_in[0];
    const float* tok   = (const float*)d_in[1];
    const float* pos   = (const float*)d_in[2];
    const float* qkv_w = (const float*)d_in[3];
    const float* qkv_b = (const float*)d_in[4];
    const float* out_w = (const float*)d_in[5];
    const float* out_b = (const float*)d_in[6];
    const float* ln1_w = (const float*)d_in[7];
    const float* ln1_b = (const float*)d_in[8];
    const float* ln2_w = (const float*)d_in[9];
    const float* ln2_b = (const float*)d_in[10];
    const float* ff1_w = (const float*)d_in[11];
    const float* ff1_b = (const float*)d_in[12];
    const float* ff2_w = (const float*)d_in[13];
    const float* ff2_b = (const float*)d_in[14];
    float* out = (float*)d_out;

    float *x, *qkv, *att, *tmp, *ff;
    int *rel, *seg;
    cudaGetSymbolAddress((void**)&x,   g_x);
    cudaGetSymbolAddress((void**)&qkv, g_qkv);
    cudaGetSymbolAddress((void**)&att, g_att);
    cudaGetSymbolAddress((void**)&tmp, g_tmp);
    cudaGetSymbolAddress((void**)&ff,  g_ff);
    cudaGetSymbolAddress((void**)&rel, g_rel);
    cudaGetSymbolAddress((void**)&seg, g_seg);

    cudaFuncSetAttribute(gemm_tf32<false>,
        cudaFuncAttributeMaxDynamicSharedMemorySize, GEMM_SMEM);
    cudaFuncSetAttribute(gemm_tf32<true>,
        cudaFuncAttributeMaxDynamicSharedMemorySize, GEMM_SMEM);
    cudaFuncSetAttribute(attn_tile_kernel,
        cudaFuncAttributeMaxDynamicSharedMemorySize, ATTN_SMEM);

    meta_kernel<<<BB, 32>>>(ids, rel, seg);
    embed_kernel<<<ROWS, 256>>>(ids, rel, tok, pos, x);

    for (int l = 0; l < NLAY; l++) {
        gemm_tf32<false><<<dim3(3*DD/128, ROWS/128), 256, GEMM_SMEM>>>(
            x, qkv_w + (size_t)l*3*DD*DD, qkv_b + (size_t)l*3*DD, qkv,
            ROWS, 3*DD, DD);

        attn_tile_kernel<<<dim3(LL/64, HH, BB), 256, ATTN_SMEM>>>(qkv, seg, att);

        gemm_tf32<false><<<dim3(DD/128, ROWS/128), 256, GEMM_SMEM>>>(
            att, out_w + (size_t)l*DD*DD, out_b + (size_t)l*DD, tmp,
            ROWS, DD, DD);

        add_ln_kernel<<<ROWS, 256>>>(x, tmp, ln1_w + (size_t)l*DD, ln1_b + (size_t)l*DD);

        gemm_tf32<true><<<dim3(DFFN/128, ROWS/128), 256, GEMM_SMEM>>>(
            x, ff1_w + (size_t)l*DFFN*DD, ff1_b + (size_t)l*DFFN, ff,
            ROWS, DFFN, DD);

        gemm_tf32<false><<<dim3(DD/128, ROWS/128), 256, GEMM_SMEM>>>(
            ff, ff2_w + (size_t)l*DD*DFFN, ff2_b + (size_t)l*DD, tmp,
            ROWS, DD, DFFN);

        add_ln_kernel<<<ROWS, 256>>>(x, tmp, ln2_w + (size_t)l*DD, ln2_b + (size_t)l*DD);
    }

    gemm_tf32<false><<<dim3((VV + 127)/128, ROWS/128), 256, GEMM_SMEM>>>(
        x, tok, nullptr, out, ROWS, VV, DD);
}

// round 5
// speedup vs baseline: 4.4578x; 1.2929x over previous
#include <cuda_runtime.h>
#include <cuda_fp16.h>
#include <math.h>
#include <stdint.h>

// Problem constants
#define BB   2
#define LL   1024
#define DD   768
#define HH   12
#define HD   64
#define NLAY 2
#define DFFN 3072
#define VV   50257
#define EOS_ID 50256
#define ROWS (BB*LL)          // 2048

// ---------------------------------------------------------------------------
// Static scratch
// ---------------------------------------------------------------------------
__device__ float g_x[ROWS*DD];
__device__ float g_qkv[ROWS*3*DD];
__device__ float g_att[ROWS*DD];
__device__ float g_tmp[ROWS*DD];
__device__ float g_ff[ROWS*DFFN];
__device__ int   g_rel[ROWS];
__device__ int   g_seg[ROWS];

// ---------------------------------------------------------------------------
// Meta + embedding
// ---------------------------------------------------------------------------
__global__ void meta_kernel(const int* __restrict__ ids, int* __restrict__ rel,
                            int* __restrict__ seg) {
    int b = blockIdx.x;
    if (threadIdx.x != 0) return;
    int last = 0, s = 0;
    for (int l = 0; l < LL; l++) {
        int id = ids[b*LL + l];
        if (id == EOS_ID) { last = l; s += 1; }
        rel[b*LL + l] = l - last;
        seg[b*LL + l] = s;
    }
}

__global__ void embed_kernel(const int* __restrict__ ids, const int* __restrict__ rel,
                             const float* __restrict__ tok, const float* __restrict__ pos,
                             float* __restrict__ x) {
    int row = blockIdx.x;
    int id = ids[row];
    int r  = rel[row];
    const float* t = tok + (size_t)id * DD;
    const float* p = pos + (size_t)r  * DD;
    const float sc = 27.712812921102035f;  // sqrt(768)
    for (int i = threadIdx.x; i < DD; i += blockDim.x)
        x[(size_t)row*DD + i] = t[i] * sc + p[i];
}

// ---------------------------------------------------------------------------
// FP16 tensor-core GEMM: C[M,N] = A[M,K] @ B[N,K]^T (+bias)(+GELU)
// Block tile 128x128, BK=32, 8 warps (4m x 2n), warp tile 32x64.
// mma.sync.m16n8k16.f32.f16.f16.f32, fp32 accumulate.
// fp16 smem (converted at store), double-buffered, one sync per k-tile.
// M%128==0, K%32==0 required. N guarded.
// ---------------------------------------------------------------------------
#define HSTR 40   // halves per row (32 data + 8 pad); 80B row stride

__device__ __forceinline__ uint32_t packh2(float x, float y) {
    __half2 h = __floats2half2_rn(x, y);
    return *reinterpret_cast<uint32_t*>(&h);
}

template<bool GELU>
__global__ __launch_bounds__(256, 2)
void gemm_f16(const float* __restrict__ A, const float* __restrict__ B,
              const float* __restrict__ bias, float* __restrict__ C,
              int M, int N, int K) {
    __shared__ __align__(16) __half SA[2][128*HSTR];
    __shared__ __align__(16) __half SB[2][128*HSTR];

    const int bm = blockIdx.y * 128;
    const int bn = blockIdx.x * 128;
    const int tid  = threadIdx.x;
    const int warp = tid >> 5;
    const int lane = tid & 31;
    const int grp  = lane >> 2;   // 0..7
    const int qid  = lane & 3;    // 0..3

    const int wm = (warp >> 1) * 32;
    const int wn = (warp & 1) * 64;

    float acc[2][8][4];
#pragma unroll
    for (int i = 0; i < 2; i++)
#pragma unroll
        for (int j = 0; j < 8; j++)
#pragma unroll
            for (int c = 0; c < 4; c++) acc[i][j][c] = 0.f;

    const int ntiles = K >> 5;
    float4 rA[4], rB[4];

    // prologue: tile 0 -> buf 0
#pragma unroll
    for (int i = 0; i < 4; i++) {
        int idx = tid + (i << 8);
        int row = idx >> 3;
        int f4  = idx & 7;
        rA[i] = *reinterpret_cast<const float4*>(A + (size_t)(bm + row) * K + f4*4);
        int gn = bn + row;
        rB[i] = (gn < N) ? *reinterpret_cast<const float4*>(B + (size_t)gn * K + f4*4)
                         : make_float4(0.f, 0.f, 0.f, 0.f);
    }
#pragma unroll
    for (int i = 0; i < 4; i++) {
        int idx = tid + (i << 8);
        int row = idx >> 3;
        int f4  = idx & 7;
        uint2 pa = make_uint2(packh2(rA[i].x, rA[i].y), packh2(rA[i].z, rA[i].w));
        *reinterpret_cast<uint2*>(&SA[0][row*HSTR + f4*4]) = pa;
        uint2 pb = make_uint2(packh2(rB[i].x, rB[i].y), packh2(rB[i].z, rB[i].w));
        *reinterpret_cast<uint2*>(&SB[0][row*HSTR + f4*4]) = pb;
    }
    __syncthreads();

    for (int t = 0; t < ntiles; t++) {
        const int cb = t & 1;
        const bool more = (t + 1 < ntiles);

        // prefetch next tile gmem -> regs
        if (more) {
            int kt = (t + 1) << 5;
#pragma unroll
            for (int i = 0; i < 4; i++) {
                int idx = tid + (i << 8);
                int row = idx >> 3;
                int f4  = idx & 7;
                rA[i] = *reinterpret_cast<const float4*>(A + (size_t)(bm + row) * K + kt + f4*4);
                int gn = bn + row;
                rB[i] = (gn < N) ? *reinterpret_cast<const float4*>(B + (size_t)gn * K + kt + f4*4)
                                 : make_float4(0.f, 0.f, 0.f, 0.f);
            }
        }

        // compute: 2 k16-steps
        const __half* As = SA[cb];
        const __half* Bs = SB[cb];
#pragma unroll
        for (int ks = 0; ks < 2; ks++) {
            int k0 = ks << 4;
            uint32_t af[2][4];
#pragma unroll
            for (int i = 0; i < 2; i++) {
                int r0 = wm + i*16 + grp;
                int cb0 = k0 + 2*qid;
                af[i][0] = *reinterpret_cast<const uint32_t*>(&As[(r0    )*HSTR + cb0    ]);
                af[i][1] = *reinterpret_cast<const uint32_t*>(&As[(r0 + 8)*HSTR + cb0    ]);
                af[i][2] = *reinterpret_cast<const uint32_t*>(&As[(r0    )*HSTR + cb0 + 8]);
                af[i][3] = *reinterpret_cast<const uint32_t*>(&As[(r0 + 8)*HSTR + cb0 + 8]);
            }
#pragma unroll
            for (int j = 0; j < 8; j++) {
                int nrow = wn + j*8 + grp;
                int cb0 = k0 + 2*qid;
                uint32_t b0 = *reinterpret_cast<const uint32_t*>(&Bs[nrow*HSTR + cb0    ]);
                uint32_t b1 = *reinterpret_cast<const uint32_t*>(&Bs[nrow*HSTR + cb0 + 8]);
#pragma unroll
                for (int i = 0; i < 2; i++) {
                    asm volatile(
                        "mma.sync.aligned.m16n8k16.row.col.f32.f16.f16.f32 "
                        "{%0,%1,%2,%3}, {%4,%5,%6,%7}, {%8,%9}, {%0,%1,%2,%3};\n"
                        : "+f"(acc[i][j][0]), "+f"(acc[i][j][1]),
                          "+f"(acc[i][j][2]), "+f"(acc[i][j][3])
                        : "r"(af[i][0]), "r"(af[i][1]), "r"(af[i][2]), "r"(af[i][3]),
                          "r"(b0), "r"(b1));
                }
            }
        }

        // store prefetched tile into the other buffer (no alias with compute buf)
        if (more) {
            const int nb = (t + 1) & 1;
#pragma unroll
            for (int i = 0; i < 4; i++) {
                int idx = tid + (i << 8);
                int row = idx >> 3;
                int f4  = idx & 7;
                uint2 pa = make_uint2(packh2(rA[i].x, rA[i].y), packh2(rA[i].z, rA[i].w));
                *reinterpret_cast<uint2*>(&SA[nb][row*HSTR + f4*4]) = pa;
                uint2 pb = make_uint2(packh2(rB[i].x, rB[i].y), packh2(rB[i].z, rB[i].w));
                *reinterpret_cast<uint2*>(&SB[nb][row*HSTR + f4*4]) = pb;
            }
        }
        __syncthreads();
    }

    // epilogue (same D layout as m16n8k8: c0,c1=(grp,2q+{0,1}), c2,c3=(grp+8,..))
#pragma unroll
    for (int i = 0; i < 2; i++) {
#pragma unroll
        for (int j = 0; j < 8; j++) {
#pragma unroll
            for (int c = 0; c < 4; c++) {
                int row = bm + wm + i*16 + grp + ((c >> 1) << 3);
                int col = bn + wn + j*8 + (qid << 1) + (c & 1);
                if (col < N) {
                    float v = acc[i][j][c];
                    if (bias) v += bias[col];
                    if (GELU) v = 0.5f * v * (1.0f + erff(v * 0.7071067811865475f));
                    C[(size_t)row * N + col] = v;
                }
            }
        }
    }
}

// ---------------------------------------------------------------------------
// Tiled flash attention (unchanged from R3)
// ---------------------------------------------------------------------------
#define APAD 68
#define ATTN_SMEM (4*64*APAD*4 + 64*4)

__global__ __launch_bounds__(256, 2)
void attn_tile_kernel(const float* __restrict__ qkv, const int* __restrict__ seg,
                      float* __restrict__ o) {
    extern __shared__ float asm_[];
    float* Qt = asm_;
    float* Kt = Qt + 64*APAD;
    float* Vs = Kt + 64*APAD;
    float* Ps = Vs + 64*APAD;
    int*  sseg = (int*)(Ps + 64*APAD);

    const int qt = blockIdx.x;
    const int h  = blockIdx.y;
    const int b  = blockIdx.z;
    const int tid = threadIdx.x;
    const int tx = tid & 15, ty = tid >> 4;
    const int q0 = qt * 64;

#pragma unroll
    for (int i = 0; i < 4; i++) {
        int idx = tid + (i << 8);
        int r = idx >> 4;
        int c = (idx & 15) << 2;
        float4 v = *reinterpret_cast<const float4*>(
            qkv + (size_t)(b*LL + q0 + r)*(3*DD) + h*HD + c);
        Qt[(c+0)*APAD + r] = v.x;
        Qt[(c+1)*APAD + r] = v.y;
        Qt[(c+2)*APAD + r] = v.z;
        Qt[(c+3)*APAD + r] = v.w;
    }
    int qseg[4];
#pragma unroll
    for (int i = 0; i < 4; i++) qseg[i] = seg[b*LL + q0 + 4*ty + i];

    float m[4], l[4], O[4][4];
#pragma unroll
    for (int i = 0; i < 4; i++) {
        m[i] = -1e30f; l[i] = 0.f;
#pragma unroll
        for (int j = 0; j < 4; j++) O[i][j] = 0.f;
    }
    __syncthreads();

    for (int kt = 0; kt <= qt; kt++) {
        const int k0 = kt * 64;
#pragma unroll
        for (int i = 0; i < 4; i++) {
            int idx = tid + (i << 8);
            int r = idx >> 4;
            int c = (idx & 15) << 2;
            const float* base = qkv + (size_t)(b*LL + k0 + r)*(3*DD) + h*HD + c;
            float4 kv = *reinterpret_cast<const float4*>(base + DD);
            Kt[(c+0)*APAD + r] = kv.x;
            Kt[(c+1)*APAD + r] = kv.y;
            Kt[(c+2)*APAD + r] = kv.z;
            Kt[(c+3)*APAD + r] = kv.w;
            float4 vv = *reinterpret_cast<const float4*>(base + 2*DD);
            *reinterpret_cast<float4*>(&Vs[r*APAD + c]) = vv;
        }
        if (tid < 64) sseg[tid] = seg[b*LL + k0 + tid];
        __syncthreads();

        float s[4][4];
#pragma unroll
        for (int i = 0; i < 4; i++)
#pragma unroll
            for (int j = 0; j < 4; j++) s[i][j] = 0.f;
#pragma unroll 8
        for (int d = 0; d < 64; d++) {
            float4 qv = *reinterpret_cast<const float4*>(&Qt[d*APAD + 4*ty]);
            float4 kv = *reinterpret_cast<const float4*>(&Kt[d*APAD + 4*tx]);
            float qa[4] = {qv.x, qv.y, qv.z, qv.w};
            float ka[4] = {kv.x, kv.y, kv.z, kv.w};
#pragma unroll
            for (int i = 0; i < 4; i++)
#pragma unroll
                for (int j = 0; j < 4; j++)
                    s[i][j] = fmaf(qa[i], ka[j], s[i][j]);
        }

#pragma unroll
        for (int i = 0; i < 4; i++) {
            int qg = q0 + 4*ty + i;
#pragma unroll
            for (int j = 0; j < 4; j++) {
                int kg = k0 + 4*tx + j;
                bool ok = (kg <= qg) && (sseg[4*tx + j] == qseg[i]);
                s[i][j] = ok ? s[i][j] * 0.125f : -1e30f;
            }
            float mt = fmaxf(fmaxf(s[i][0], s[i][1]), fmaxf(s[i][2], s[i][3]));
#pragma unroll
            for (int off = 1; off < 16; off <<= 1)
                mt = fmaxf(mt, __shfl_xor_sync(0xffffffffu, mt, off));
            float mn = fmaxf(m[i], mt);
            float fac = __expf(m[i] - mn);
            m[i] = mn;
            l[i] *= fac;
#pragma unroll
            for (int j = 0; j < 4; j++) O[i][j] *= fac;
            float rs = 0.f;
#pragma unroll
            for (int j = 0; j < 4; j++) {
                float p = __expf(s[i][j] - mn);
                s[i][j] = p;
                rs += p;
            }
#pragma unroll
            for (int off = 1; off < 16; off <<= 1)
                rs += __shfl_xor_sync(0xffffffffu, rs, off);
            l[i] += rs;
        }

#pragma unroll
        for (int i = 0; i < 4; i++)
            *reinterpret_cast<float4*>(&Ps[(4*ty + i)*APAD + 4*tx]) =
                make_float4(s[i][0], s[i][1], s[i][2], s[i][3]);
        __syncthreads();

#pragma unroll 4
        for (int k = 0; k < 64; k++) {
            float pa[4];
#pragma unroll
            for (int i = 0; i < 4; i++) pa[i] = Ps[(4*ty + i)*APAD + k];
            float4 vv = *reinterpret_cast<const float4*>(&Vs[k*APAD + 4*tx]);
            float va[4] = {vv.x, vv.y, vv.z, vv.w};
#pragma unroll
            for (int i = 0; i < 4; i++)
#pragma unroll
                for (int j = 0; j < 4; j++)
                    O[i][j] = fmaf(pa[i], va[j], O[i][j]);
        }
        __syncthreads();
    }

#pragma unroll
    for (int i = 0; i < 4; i++) {
        float inv = 1.0f / l[i];
        float4 ov = make_float4(O[i][0]*inv, O[i][1]*inv, O[i][2]*inv, O[i][3]*inv);
        *reinterpret_cast<float4*>(
            o + (size_t)(b*LL + q0 + 4*ty + i)*DD + h*HD + 4*tx) = ov;
    }
}

// ---------------------------------------------------------------------------
// Block reduction + fused add+LN
// ---------------------------------------------------------------------------
__device__ __forceinline__ float block_sum256(float v, volatile float* red) {
#pragma unroll
    for (int o = 16; o; o >>= 1) v += __shfl_xor_sync(0xffffffffu, v, o);
    if ((threadIdx.x & 31) == 0) red[threadIdx.x >> 5] = v;
    __syncthreads();
    if (threadIdx.x == 0) {
        float s = red[0];
#pragma unroll
        for (int i = 1; i < 8; i++) s += red[i];
        red[0] = s;
    }
    __syncthreads();
    float r = red[0];
    __syncthreads();
    return r;
}

__global__ __launch_bounds__(256)
void add_ln_kernel(float* __restrict__ x, const float* __restrict__ r,
                   const float* __restrict__ w, const float* __restrict__ b) {
    int row = blockIdx.x;
    int tid = threadIdx.x;
    __shared__ float buf[DD];
    __shared__ float red[8];

    float s = 0.f;
    for (int i = tid; i < DD; i += 256) {
        float v = x[(size_t)row*DD + i] + r[(size_t)row*DD + i];
        buf[i] = v;
        s += v;
    }
    __syncthreads();
    float mean = block_sum256(s, red) * (1.0f / DD);

    float vs = 0.f;
    for (int i = tid; i < DD; i += 256) {
        float d = buf[i] - mean;
        vs += d * d;
    }
    float var = block_sum256(vs, red) * (1.0f / DD);
    float inv = rsqrtf(var + 1e-5f);

    for (int i = tid; i < DD; i += 256)
        x[(size_t)row*DD + i] = (buf[i] - mean) * inv * w[i] + b[i];
}

// ---------------------------------------------------------------------------
// Host launcher
// ---------------------------------------------------------------------------
extern "C" void kernel_launch(void* const* d_in, const int* in_sizes, int n_in,
                              void* d_out, int out_size) {
    const int*   ids   = (const int*)  d_in[0];
    const float* tok   = (const float*)d_in[1];
    const float* pos   = (const float*)d_in[2];
    const float* qkv_w = (const float*)d_in[3];
    const float* qkv_b = (const float*)d_in[4];
    const float* out_w = (const float*)d_in[5];
    const float* out_b = (const float*)d_in[6];
    const float* ln1_w = (const float*)d_in[7];
    const float* ln1_b = (const float*)d_in[8];
    const float* ln2_w = (const float*)d_in[9];
    const float* ln2_b = (const float*)d_in[10];
    const float* ff1_w = (const float*)d_in[11];
    const float* ff1_b = (const float*)d_in[12];
    const float* ff2_w = (const float*)d_in[13];
    const float* ff2_b = (const float*)d_in[14];
    float* out = (float*)d_out;

    float *x, *qkv, *att, *tmp, *ff;
    int *rel, *seg;
    cudaGetSymbolAddress((void**)&x,   g_x);
    cudaGetSymbolAddress((void**)&qkv, g_qkv);
    cudaGetSymbolAddress((void**)&att, g_att);
    cudaGetSymbolAddress((void**)&tmp, g_tmp);
    cudaGetSymbolAddress((void**)&ff,  g_ff);
    cudaGetSymbolAddress((void**)&rel, g_rel);
    cudaGetSymbolAddress((void**)&seg, g_seg);

    cudaFuncSetAttribute(attn_tile_kernel,
        cudaFuncAttributeMaxDynamicSharedMemorySize, ATTN_SMEM);

    meta_kernel<<<BB, 32>>>(ids, rel, seg);
    embed_kernel<<<ROWS, 256>>>(ids, rel, tok, pos, x);

    for (int l = 0; l < NLAY; l++) {
        gemm_f16<false><<<dim3(3*DD/128, ROWS/128), 256>>>(
            x, qkv_w + (size_t)l*3*DD*DD, qkv_b + (size_t)l*3*DD, qkv,
            ROWS, 3*DD, DD);

        attn_tile_kernel<<<dim3(LL/64, HH, BB), 256, ATTN_SMEM>>>(qkv, seg, att);

        gemm_f16<false><<<dim3(DD/128, ROWS/128), 256>>>(
            att, out_w + (size_t)l*DD*DD, out_b + (size_t)l*DD, tmp,
            ROWS, DD, DD);

        add_ln_kernel<<<ROWS, 256>>>(x, tmp, ln1_w + (size_t)l*DD, ln1_b + (size_t)l*DD);

        gemm_f16<true><<<dim3(DFFN/128, ROWS/128), 256>>>(
            x, ff1_w + (size_t)l*DFFN*DD, ff1_b + (size_t)l*DFFN, ff,
            ROWS, DFFN, DD);

        gemm_f16<false><<<dim3(DD/128, ROWS/128), 256>>>(
            ff, ff2_w + (size_t)l*DD*DFFN, ff2_b + (size_t)l*DD, tmp,
            ROWS, DD, DFFN);

        add_ln_kernel<<<ROWS, 256>>>(x, tmp, ln2_w + (size_t)l*DD, ln2_b + (size_t)l*DD);
    }

    gemm_f16<false><<<dim3((VV + 127)/128, ROWS/128), 256>>>(
        x, tok, nullptr, out, ROWS, VV, DD);
}

// round 7
// speedup vs baseline: 4.5402x; 1.0185x over previous
#include <cuda_runtime.h>
#include <cuda_fp16.h>
#include <math.h>
#include <stdint.h>

// Problem constants
#define BB   2
#define LL   1024
#define DD   768
#define HH   12
#define HD   64
#define NLAY 2
#define DFFN 3072
#define VV   50257
#define EOS_ID 50256
#define ROWS (BB*LL)          // 2048

// ---------------------------------------------------------------------------
// Static scratch
// ---------------------------------------------------------------------------
__device__ float g_x[ROWS*DD];
__device__ float g_qkv[ROWS*3*DD];
__device__ float g_att[ROWS*DD];
__device__ float g_tmp[ROWS*DD];
__device__ float g_ff[ROWS*DFFN];
__device__ int   g_rel[ROWS];
__device__ int   g_seg[ROWS];

__device__ __forceinline__ uint32_t smem_u32(const void* p) {
    uint32_t a;
    asm("{ .reg .u64 t; cvta.to.shared.u64 t, %1; cvt.u32.u64 %0, t; }"
        : "=r"(a) : "l"(p));
    return a;
}

// ---------------------------------------------------------------------------
// Meta + embedding
// ---------------------------------------------------------------------------
__global__ void meta_kernel(const int* __restrict__ ids, int* __restrict__ rel,
                            int* __restrict__ seg) {
    int b = blockIdx.x;
    if (threadIdx.x != 0) return;
    int last = 0, s = 0;
    for (int l = 0; l < LL; l++) {
        int id = ids[b*LL + l];
        if (id == EOS_ID) { last = l; s += 1; }
        rel[b*LL + l] = l - last;
        seg[b*LL + l] = s;
    }
}

__global__ void embed_kernel(const int* __restrict__ ids, const int* __restrict__ rel,
                             const float* __restrict__ tok, const float* __restrict__ pos,
                             float* __restrict__ x) {
    int row = blockIdx.x;
    int id = ids[row];
    int r  = rel[row];
    const float* t = tok + (size_t)id * DD;
    const float* p = pos + (size_t)r  * DD;
    const float sc = 27.712812921102035f;  // sqrt(768)
    for (int i = threadIdx.x; i < DD; i += blockDim.x)
        x[(size_t)row*DD + i] = t[i] * sc + p[i];
}

// ---------------------------------------------------------------------------
// FP16 tensor-core GEMM: C[M,N] = A[M,K] @ B[N,K]^T (+bias)(+GELU)
// Block tile 128x128, BK=32, 8 warps (4m x 2n), warp tile 32x64.
// ldmatrix.x4 fragment loads, fp16 smem double-buffered, m16n8k16 mma.
// Grid: x = M-tile (fast -> B reuse in L2), y = N-tile.
// M%128==0, K%32==0 required. N guarded.
// ---------------------------------------------------------------------------
#define HSTR 40   // halves per smem row (32 data + 8 pad)

__device__ __forceinline__ uint32_t packh2(float x, float y) {
    __half2 h = __floats2half2_rn(x, y);
    return *reinterpret_cast<uint32_t*>(&h);
}

__device__ __forceinline__ void ldsm_x4(uint32_t addr, uint32_t& r0, uint32_t& r1,
                                        uint32_t& r2, uint32_t& r3) {
    asm volatile("ldmatrix.sync.aligned.m8n8.x4.shared.b16 {%0,%1,%2,%3}, [%4];"
                 : "=r"(r0), "=r"(r1), "=r"(r2), "=r"(r3) : "r"(addr));
}

template<bool GELU>
__global__ __launch_bounds__(256, 2)
void gemm_f16(const float* __restrict__ A, const float* __restrict__ B,
              const float* __restrict__ bias, float* __restrict__ C,
              int M, int N, int K) {
    __shared__ __align__(16) __half SA[2][128*HSTR];
    __shared__ __align__(16) __half SB[2][128*HSTR];

    const int bm = blockIdx.x * 128;   // M fast axis
    const int bn = blockIdx.y * 128;
    const int tid  = threadIdx.x;
    const int warp = tid >> 5;
    const int lane = tid & 31;
    const int grp  = lane >> 2;
    const int qid  = lane & 3;

    const int wm = (warp >> 1) * 32;
    const int wn = (warp & 1) * 64;

    // ldmatrix per-lane byte offsets (within a buffer)
    const int lrow  = lane & 15;
    const int lcol8 = (lane >> 4) << 3;     // 0 or 8 halves
    uint32_t aoff[2], boff[4];
#pragma unroll
    for (int i = 0; i < 2; i++)
        aoff[i] = ((wm + i*16 + lrow) * HSTR + lcol8) * 2;
#pragma unroll
    for (int p = 0; p < 4; p++)
        boff[p] = ((wn + p*16 + lrow) * HSTR + lcol8) * 2;

    const uint32_t sa0 = smem_u32(&SA[0][0]), sa1 = smem_u32(&SA[1][0]);
    const uint32_t sb0 = smem_u32(&SB[0][0]), sb1 = smem_u32(&SB[1][0]);

    float acc[2][8][4];
#pragma unroll
    for (int i = 0; i < 2; i++)
#pragma unroll
        for (int j = 0; j < 8; j++)
#pragma unroll
            for (int c = 0; c < 4; c++) acc[i][j][c] = 0.f;

    const int ntiles = K >> 5;
    float4 rA[4], rB[4];

    // prologue: tile 0 -> buf 0
#pragma unroll
    for (int i = 0; i < 4; i++) {
        int idx = tid + (i << 8);
        int row = idx >> 3;
        int f4  = idx & 7;
        rA[i] = *reinterpret_cast<const float4*>(A + (size_t)(bm + row) * K + f4*4);
        int gn = bn + row;
        rB[i] = (gn < N) ? *reinterpret_cast<const float4*>(B + (size_t)gn * K + f4*4)
                         : make_float4(0.f, 0.f, 0.f, 0.f);
    }
#pragma unroll
    for (int i = 0; i < 4; i++) {
        int idx = tid + (i << 8);
        int row = idx >> 3;
        int f4  = idx & 7;
        uint2 pa = make_uint2(packh2(rA[i].x, rA[i].y), packh2(rA[i].z, rA[i].w));
        *reinterpret_cast<uint2*>(&SA[0][row*HSTR + f4*4]) = pa;
        uint2 pb = make_uint2(packh2(rB[i].x, rB[i].y), packh2(rB[i].z, rB[i].w));
        *reinterpret_cast<uint2*>(&SB[0][row*HSTR + f4*4]) = pb;
    }
    __syncthreads();

    for (int t = 0; t < ntiles; t++) {
        const int cb = t & 1;
        const bool more = (t + 1 < ntiles);

        // prefetch next tile gmem -> regs
        if (more) {
            int kt = (t + 1) << 5;
#pragma unroll
            for (int i = 0; i < 4; i++) {
                int idx = tid + (i << 8);
                int row = idx >> 3;
                int f4  = idx & 7;
                rA[i] = *reinterpret_cast<const float4*>(A + (size_t)(bm + row) * K + kt + f4*4);
                int gn = bn + row;
                rB[i] = (gn < N) ? *reinterpret_cast<const float4*>(B + (size_t)gn * K + kt + f4*4)
                                 : make_float4(0.f, 0.f, 0.f, 0.f);
            }
        }

        // compute: 2 k16-steps, ldmatrix fragments
        const uint32_t sa = cb ? sa1 : sa0;
        const uint32_t sb = cb ? sb1 : sb0;
#pragma unroll
        for (int ks = 0; ks < 2; ks++) {
            const uint32_t kb = ks * 32;   // 16 halves = 32 bytes
            uint32_t af[2][4];
#pragma unroll
            for (int i = 0; i < 2; i++)
                ldsm_x4(sa + aoff[i] + kb, af[i][0], af[i][1], af[i][2], af[i][3]);
#pragma unroll
            for (int p = 0; p < 4; p++) {
                uint32_t bf[4];
                ldsm_x4(sb + boff[p] + kb, bf[0], bf[1], bf[2], bf[3]);
#pragma unroll
                for (int i = 0; i < 2; i++) {
                    asm volatile(
                        "mma.sync.aligned.m16n8k16.row.col.f32.f16.f16.f32 "
                        "{%0,%1,%2,%3}, {%4,%5,%6,%7}, {%8,%9}, {%0,%1,%2,%3};\n"
                        : "+f"(acc[i][2*p][0]), "+f"(acc[i][2*p][1]),
                          "+f"(acc[i][2*p][2]), "+f"(acc[i][2*p][3])
                        : "r"(af[i][0]), "r"(af[i][1]), "r"(af[i][2]), "r"(af[i][3]),
                          "r"(bf[0]), "r"(bf[2]));
                    asm volatile(
                        "mma.sync.aligned.m16n8k16.row.col.f32.f16.f16.f32 "
                        "{%0,%1,%2,%3}, {%4,%5,%6,%7}, {%8,%9}, {%0,%1,%2,%3};\n"
                        : "+f"(acc[i][2*p+1][0]), "+f"(acc[i][2*p+1][1]),
                          "+f"(acc[i][2*p+1][2]), "+f"(acc[i][2*p+1][3])
                        : "r"(af[i][0]), "r"(af[i][1]), "r"(af[i][2]), "r"(af[i][3]),
                          "r"(bf[1]), "r"(bf[3]));
                }
            }
        }

        // store prefetched tile into the other buffer
        if (more) {
            const int nb = (t + 1) & 1;
#pragma unroll
            for (int i = 0; i < 4; i++) {
                int idx = tid + (i << 8);
                int row = idx >> 3;
                int f4  = idx & 7;
                uint2 pa = make_uint2(packh2(rA[i].x, rA[i].y), packh2(rA[i].z, rA[i].w));
                *reinterpret_cast<uint2*>(&SA[nb][row*HSTR + f4*4]) = pa;
                uint2 pb = make_uint2(packh2(rB[i].x, rB[i].y), packh2(rB[i].z, rB[i].w));
                *reinterpret_cast<uint2*>(&SB[nb][row*HSTR + f4*4]) = pb;
            }
        }
        __syncthreads();
    }

    // epilogue: paired stores only when 8B-aligned (N odd -> odd rows misalign)
    const bool evenN = (N & 1) == 0;
#pragma unroll
    for (int i = 0; i < 2; i++) {
#pragma unroll
        for (int j = 0; j < 8; j++) {
#pragma unroll
            for (int pr = 0; pr < 2; pr++) {
                int row = bm + wm + i*16 + grp + pr*8;
                int col = bn + wn + j*8 + (qid << 1);
                float v0 = acc[i][j][2*pr + 0];
                float v1 = acc[i][j][2*pr + 1];
                if (bias) { v0 += bias[col]; if (col + 1 < N) v1 += bias[col + 1]; }
                if (GELU) {
                    v0 = 0.5f * v0 * (1.0f + erff(v0 * 0.7071067811865475f));
                    v1 = 0.5f * v1 * (1.0f + erff(v1 * 0.7071067811865475f));
                }
                size_t base = (size_t)row * N + col;
                if (col + 1 < N) {
                    if (evenN) {
                        *reinterpret_cast<float2*>(&C[base]) = make_float2(v0, v1);
                    } else {
                        C[base] = v0;
                        C[base + 1] = v1;
                    }
                } else if (col < N) {
                    C[base] = v0;
                }
            }
        }
    }
}

// ---------------------------------------------------------------------------
// Tiled flash attention (unchanged)
// ---------------------------------------------------------------------------
#define APAD 68
#define ATTN_SMEM (4*64*APAD*4 + 64*4)

__global__ __launch_bounds__(256, 2)
void attn_tile_kernel(const float* __restrict__ qkv, const int* __restrict__ seg,
                      float* __restrict__ o) {
    extern __shared__ float asm_[];
    float* Qt = asm_;
    float* Kt = Qt + 64*APAD;
    float* Vs = Kt + 64*APAD;
    float* Ps = Vs + 64*APAD;
    int*  sseg = (int*)(Ps + 64*APAD);

    const int qt = blockIdx.x;
    const int h  = blockIdx.y;
    const int b  = blockIdx.z;
    const int tid = threadIdx.x;
    const int tx = tid & 15, ty = tid >> 4;
    const int q0 = qt * 64;

#pragma unroll
    for (int i = 0; i < 4; i++) {
        int idx = tid + (i << 8);
        int r = idx >> 4;
        int c = (idx & 15) << 2;
        float4 v = *reinterpret_cast<const float4*>(
            qkv + (size_t)(b*LL + q0 + r)*(3*DD) + h*HD + c);
        Qt[(c+0)*APAD + r] = v.x;
        Qt[(c+1)*APAD + r] = v.y;
        Qt[(c+2)*APAD + r] = v.z;
        Qt[(c+3)*APAD + r] = v.w;
    }
    int qseg[4];
#pragma unroll
    for (int i = 0; i < 4; i++) qseg[i] = seg[b*LL + q0 + 4*ty + i];

    float m[4], l[4], O[4][4];
#pragma unroll
    for (int i = 0; i < 4; i++) {
        m[i] = -1e30f; l[i] = 0.f;
#pragma unroll
        for (int j = 0; j < 4; j++) O[i][j] = 0.f;
    }
    __syncthreads();

    for (int kt = 0; kt <= qt; kt++) {
        const int k0 = kt * 64;
#pragma unroll
        for (int i = 0; i < 4; i++) {
            int idx = tid + (i << 8);
            int r = idx >> 4;
            int c = (idx & 15) << 2;
            const float* base = qkv + (size_t)(b*LL + k0 + r)*(3*DD) + h*HD + c;
            float4 kv = *reinterpret_cast<const float4*>(base + DD);
            Kt[(c+0)*APAD + r] = kv.x;
            Kt[(c+1)*APAD + r] = kv.y;
            Kt[(c+2)*APAD + r] = kv.z;
            Kt[(c+3)*APAD + r] = kv.w;
            float4 vv = *reinterpret_cast<const float4*>(base + 2*DD);
            *reinterpret_cast<float4*>(&Vs[r*APAD + c]) = vv;
        }
        if (tid < 64) sseg[tid] = seg[b*LL + k0 + tid];
        __syncthreads();

        float s[4][4];
#pragma unroll
        for (int i = 0; i < 4; i++)
#pragma unroll
            for (int j = 0; j < 4; j++) s[i][j] = 0.f;
#pragma unroll 8
        for (int d = 0; d < 64; d++) {
            float4 qv = *reinterpret_cast<const float4*>(&Qt[d*APAD + 4*ty]);
            float4 kv = *reinterpret_cast<const float4*>(&Kt[d*APAD + 4*tx]);
            float qa[4] = {qv.x, qv.y, qv.z, qv.w};
            float ka[4] = {kv.x, kv.y, kv.z, kv.w};
#pragma unroll
            for (int i = 0; i < 4; i++)
#pragma unroll
                for (int j = 0; j < 4; j++)
                    s[i][j] = fmaf(qa[i], ka[j], s[i][j]);
        }

#pragma unroll
        for (int i = 0; i < 4; i++) {
            int qg = q0 + 4*ty + i;
#pragma unroll
            for (int j = 0; j < 4; j++) {
                int kg = k0 + 4*tx + j;
                bool ok = (kg <= qg) && (sseg[4*tx + j] == qseg[i]);
                s[i][j] = ok ? s[i][j] * 0.125f : -1e30f;
            }
            float mt = fmaxf(fmaxf(s[i][0], s[i][1]), fmaxf(s[i][2], s[i][3]));
#pragma unroll
            for (int off = 1; off < 16; off <<= 1)
                mt = fmaxf(mt, __shfl_xor_sync(0xffffffffu, mt, off));
            float mn = fmaxf(m[i], mt);
            float fac = __expf(m[i] - mn);
            m[i] = mn;
            l[i] *= fac;
#pragma unroll
            for (int j = 0; j < 4; j++) O[i][j] *= fac;
            float rs = 0.f;
#pragma unroll
            for (int j = 0; j < 4; j++) {
                float p = __expf(s[i][j] - mn);
                s[i][j] = p;
                rs += p;
            }
#pragma unroll
            for (int off = 1; off < 16; off <<= 1)
                rs += __shfl_xor_sync(0xffffffffu, rs, off);
            l[i] += rs;
        }

#pragma unroll
        for (int i = 0; i < 4; i++)
            *reinterpret_cast<float4*>(&Ps[(4*ty + i)*APAD + 4*tx]) =
                make_float4(s[i][0], s[i][1], s[i][2], s[i][3]);
        __syncthreads();

#pragma unroll 4
        for (int k = 0; k < 64; k++) {
            float pa[4];
#pragma unroll
            for (int i = 0; i < 4; i++) pa[i] = Ps[(4*ty + i)*APAD + k];
            float4 vv = *reinterpret_cast<const float4*>(&Vs[k*APAD + 4*tx]);
            float va[4] = {vv.x, vv.y, vv.z, vv.w};
#pragma unroll
            for (int i = 0; i < 4; i++)
#pragma unroll
                for (int j = 0; j < 4; j++)
                    O[i][j] = fmaf(pa[i], va[j], O[i][j]);
        }
        __syncthreads();
    }

#pragma unroll
    for (int i = 0; i < 4; i++) {
        float inv = 1.0f / l[i];
        float4 ov = make_float4(O[i][0]*inv, O[i][1]*inv, O[i][2]*inv, O[i][3]*inv);
        *reinterpret_cast<float4*>(
            o + (size_t)(b*LL + q0 + 4*ty + i)*DD + h*HD + 4*tx) = ov;
    }
}

// ---------------------------------------------------------------------------
// Block reduction + fused add+LN
// ---------------------------------------------------------------------------
__device__ __forceinline__ float block_sum256(float v, volatile float* red) {
#pragma unroll
    for (int o = 16; o; o >>= 1) v += __shfl_xor_sync(0xffffffffu, v, o);
    if ((threadIdx.x & 31) == 0) red[threadIdx.x >> 5] = v;
    __syncthreads();
    if (threadIdx.x == 0) {
        float s = red[0];
#pragma unroll
        for (int i = 1; i < 8; i++) s += red[i];
        red[0] = s;
    }
    __syncthreads();
    float r = red[0];
    __syncthreads();
    return r;
}

__global__ __launch_bounds__(256)
void add_ln_kernel(float* __restrict__ x, const float* __restrict__ r,
                   const float* __restrict__ w, const float* __restrict__ b) {
    int row = blockIdx.x;
    int tid = threadIdx.x;
    __shared__ float buf[DD];
    __shared__ float red[8];

    float s = 0.f;
    for (int i = tid; i < DD; i += 256) {
        float v = x[(size_t)row*DD + i] + r[(size_t)row*DD + i];
        buf[i] = v;
        s += v;
    }
    __syncthreads();
    float mean = block_sum256(s, red) * (1.0f / DD);

    float vs = 0.f;
    for (int i = tid; i < DD; i += 256) {
        float d = buf[i] - mean;
        vs += d * d;
    }
    float var = block_sum256(vs, red) * (1.0f / DD);
    float inv = rsqrtf(var + 1e-5f);

    for (int i = tid; i < DD; i += 256)
        x[(size_t)row*DD + i] = (buf[i] - mean) * inv * w[i] + b[i];
}

// ---------------------------------------------------------------------------
// Host launcher
// ---------------------------------------------------------------------------
extern "C" void kernel_launch(void* const* d_in, const int* in_sizes, int n_in,
                              void* d_out, int out_size) {
    const int*   ids   = (const int*)  d_in[0];
    const float* tok   = (const float*)d_in[1];
    const float* pos   = (const float*)d_in[2];
    const float* qkv_w = (const float*)d_in[3];
    const float* qkv_b = (const float*)d_in[4];
    const float* out_w = (const float*)d_in[5];
    const float* out_b = (const float*)d_in[6];
    const float* ln1_w = (const float*)d_in[7];
    const float* ln1_b = (const float*)d_in[8];
    const float* ln2_w = (const float*)d_in[9];
    const float* ln2_b = (const float*)d_in[10];
    const float* ff1_w = (const float*)d_in[11];
    const float* ff1_b = (const float*)d_in[12];
    const float* ff2_w = (const float*)d_in[13];
    const float* ff2_b = (const float*)d_in[14];
    float* out = (float*)d_out;

    float *x, *qkv, *att, *tmp, *ff;
    int *rel, *seg;
    cudaGetSymbolAddress((void**)&x,   g_x);
    cudaGetSymbolAddress((void**)&qkv, g_qkv);
    cudaGetSymbolAddress((void**)&att, g_att);
    cudaGetSymbolAddress((void**)&tmp, g_tmp);
    cudaGetSymbolAddress((void**)&ff,  g_ff);
    cudaGetSymbolAddress((void**)&rel, g_rel);
    cudaGetSymbolAddress((void**)&seg, g_seg);

    cudaFuncSetAttribute(attn_tile_kernel,
        cudaFuncAttributeMaxDynamicSharedMemorySize, ATTN_SMEM);

    meta_kernel<<<BB, 32>>>(ids, rel, seg);
    embed_kernel<<<ROWS, 256>>>(ids, rel, tok, pos, x);

    const int MT = ROWS / 128;  // 16, fast axis for B reuse

    for (int l = 0; l < NLAY; l++) {
        gemm_f16<false><<<dim3(MT, 3*DD/128), 256>>>(
            x, qkv_w + (size_t)l*3*DD*DD, qkv_b + (size_t)l*3*DD, qkv,
            ROWS, 3*DD, DD);

        attn_tile_kernel<<<dim3(LL/64, HH, BB), 256, ATTN_SMEM>>>(qkv, seg, att);

        gemm_f16<false><<<dim3(MT, DD/128), 256>>>(
            att, out_w + (size_t)l*DD*DD, out_b + (size_t)l*DD, tmp,
            ROWS, DD, DD);

        add_ln_kernel<<<ROWS, 256>>>(x, tmp, ln1_w + (size_t)l*DD, ln1_b + (size_t)l*DD);

        gemm_f16<true><<<dim3(MT, DFFN/128), 256>>>(
            x, ff1_w + (size_t)l*DFFN*DD, ff1_b + (size_t)l*DFFN, ff,
            ROWS, DFFN, DD);

        gemm_f16<false><<<dim3(MT, DD/128), 256>>>(
            ff, ff2_w + (size_t)l*DD*DFFN, ff2_b + (size_t)l*DD, tmp,
            ROWS, DD, DFFN);

        add_ln_kernel<<<ROWS, 256>>>(x, tmp, ln2_w + (size_t)l*DD, ln2_b + (size_t)l*DD);
    }

    gemm_f16<false><<<dim3(MT, (VV + 127)/128), 256>>>(
        x, tok, nullptr, out, ROWS, VV, DD);
}